// round 7
// baseline (speedup 1.0000x reference)
#include <cuda_runtime.h>
#include <cuda_bf16.h>
#include <cstddef>

#define NN 100000
#define EE 3200000

typedef unsigned long long ull;

// ---------------- packed fp32x2 helpers (Blackwell FFMA2) --------------------
__device__ __forceinline__ ull ffma2(ull a, ull b, ull c) {
    ull d;
    asm("fma.rn.f32x2 %0, %1, %2, %3;" : "=l"(d) : "l"(a), "l"(b), "l"(c));
    return d;
}
__device__ __forceinline__ ull dup2(float v) {
    ull d;
    asm("mov.b64 %0, {%1, %1};" : "=l"(d) : "r"(__float_as_uint(v)));
    return d;
}
__device__ __forceinline__ float2 unpk(ull v) {
    float2 f;
    asm("mov.b64 {%0, %1}, %2;" : "=f"(f.x), "=f"(f.y) : "l"(v));
    return f;
}

// ---------------- scratch (static device allocations; no cudaMalloc) ----------
__device__ float g_H[NN * 32];        // layer0: x @ Wn0
__device__ float g_A[NN * 32];        // layer0: S = x@Ws0+bn0 ; layers 1/2: raw aggregate
__device__ float g_L[3][NN * 32];     // per-layer outputs (kept for concat)
__device__ float g_P[NN * 10];        // partial FC logits (x part + bias)
__device__ int   g_deg[NN];
__device__ int   g_rowptr[NN + 1];
__device__ int   g_rank[EE];          // edge's rank within its dst bucket
__device__ int   g_csrc[EE];          // CSR-by-dst: source node ids

// ---------------- CSR build --------------------------------------------------
__global__ void count_k(const int* __restrict__ dst) {
    int e4 = blockIdx.x * blockDim.x + threadIdx.x;
    if (e4 < EE / 4) {
        int4 d = ((const int4*)dst)[e4];
        int4 r;
        r.x = atomicAdd(&g_deg[d.x], 1);
        r.y = atomicAdd(&g_deg[d.y], 1);
        r.z = atomicAdd(&g_deg[d.z], 1);
        r.w = atomicAdd(&g_deg[d.w], 1);
        ((int4*)g_rank)[e4] = r;
    }
}

__global__ void scan_k() {
    const int T = 1024;
    const int chunk = (NN + T - 1) / T;   // 98
    int t = threadIdx.x;
    int start = t * chunk;
    int end = start + chunk;
    if (end > NN) end = NN;

    int s = 0;
    for (int i = start; i < end; i++) s += g_deg[i];

    __shared__ int sums[T];
    sums[t] = s;
    __syncthreads();
    for (int off = 1; off < T; off <<= 1) {
        int v = (t >= off) ? sums[t - off] : 0;
        __syncthreads();
        sums[t] += v;
        __syncthreads();
    }
    int run = (t == 0) ? 0 : sums[t - 1];
    for (int i = start; i < end; i++) {
        g_rowptr[i] = run;
        run += g_deg[i];
    }
    if (start < NN && end == NN) g_rowptr[NN] = run;
}

__global__ void fill_k(const int* __restrict__ src, const int* __restrict__ dst) {
    int e4 = blockIdx.x * blockDim.x + threadIdx.x;
    if (e4 < EE / 4) {
        int4 s = ((const int4*)src)[e4];
        int4 d = ((const int4*)dst)[e4];
        int4 r = ((const int4*)g_rank)[e4];
        g_csrc[g_rowptr[d.x] + r.x] = s.x;
        g_csrc[g_rowptr[d.y] + r.y] = s.y;
        g_csrc[g_rowptr[d.z] + r.z] = s.z;
        g_csrc[g_rowptr[d.w] + r.w] = s.w;
    }
}

// ---------------- layer0 GEMM: [H | S] = X @ [Wn | Ws] (+bn on S) ------------
// 128 nodes x 64 cols per block of 128 threads; thread = 8 nodes x 8 cols,
// computed as 4 node-pairs via packed FFMA2. Weights stored dup'd in shared.
__global__ void __launch_bounds__(128) gemm0_k(const float* __restrict__ X,
                       const float* __restrict__ Wn,
                       const float* __restrict__ Ws,
                       const float* __restrict__ bn,
                       float* __restrict__ H, float* __restrict__ S) {
    __shared__ __align__(16) float xs[32][132];   // [k][node]
    __shared__ __align__(16) ull   ws2[32][64];   // [k][col] (w,w) pairs
    __shared__ float bn_s[32];

    int t = threadIdx.x;
    int base = blockIdx.x * 128;
    if (t < 32) bn_s[t] = bn[t];

    int tm = t & 15, tn = t >> 4;
    int m0 = tm * 8, n0 = tn * 8;

    ull acc[4][8];
#pragma unroll
    for (int p = 0; p < 4; p++)
#pragma unroll
        for (int j = 0; j < 8; j++) acc[p][j] = 0ull;

    for (int k0 = 0; k0 < 128; k0 += 32) {
        __syncthreads();
#pragma unroll
        for (int i = t; i < 2048; i += 128) {
            int k = i >> 6, n = i & 63;
            float w = (n < 32) ? Wn[(k0 + k) * 32 + n]
                               : Ws[(k0 + k) * 32 + (n - 32)];
            ws2[k][n] = dup2(w);
        }
#pragma unroll
        for (int e = t; e < 1024; e += 128) {
            int node = e >> 3, g = e & 7;
            int gn = base + node;
            float4 v = make_float4(0.f, 0.f, 0.f, 0.f);
            if (gn < NN) v = *(const float4*)(X + (size_t)gn * 128 + k0 + g * 4);
            xs[g * 4 + 0][node] = v.x;
            xs[g * 4 + 1][node] = v.y;
            xs[g * 4 + 2][node] = v.z;
            xs[g * 4 + 3][node] = v.w;
        }
        __syncthreads();
#pragma unroll
        for (int k = 0; k < 32; k++) {
            ulonglong2 a01 = *(const ulonglong2*)&xs[k][m0];
            ulonglong2 a23 = *(const ulonglong2*)&xs[k][m0 + 4];
            ull av[4] = {a01.x, a01.y, a23.x, a23.y};
            const ulonglong2* wr = (const ulonglong2*)&ws2[k][n0];
            ulonglong2 b01 = wr[0], b23 = wr[1], b45 = wr[2], b67 = wr[3];
            ull bv[8] = {b01.x, b01.y, b23.x, b23.y, b45.x, b45.y, b67.x, b67.y};
#pragma unroll
            for (int p = 0; p < 4; p++)
#pragma unroll
                for (int j = 0; j < 8; j++)
                    acc[p][j] = ffma2(av[p], bv[j], acc[p][j]);
        }
    }

    bool isS = (tn >= 4);
    int nc = isS ? (n0 - 32) : n0;
    float bias[8];
#pragma unroll
    for (int j = 0; j < 8; j++) bias[j] = isS ? bn_s[nc + j] : 0.f;
    float* dstbase = isS ? S : H;

#pragma unroll
    for (int p = 0; p < 4; p++) {
        int gn0 = base + m0 + 2 * p;
        float2 c[8];
#pragma unroll
        for (int j = 0; j < 8; j++) c[j] = unpk(acc[p][j]);
        if (gn0 < NN) {
            float4 r0 = make_float4(c[0].x + bias[0], c[1].x + bias[1],
                                    c[2].x + bias[2], c[3].x + bias[3]);
            float4 r1 = make_float4(c[4].x + bias[4], c[5].x + bias[5],
                                    c[6].x + bias[6], c[7].x + bias[7]);
            *(float4*)(dstbase + (size_t)gn0 * 32 + nc)     = r0;
            *(float4*)(dstbase + (size_t)gn0 * 32 + nc + 4) = r1;
        }
        if (gn0 + 1 < NN) {
            float4 r0 = make_float4(c[0].y + bias[0], c[1].y + bias[1],
                                    c[2].y + bias[2], c[3].y + bias[3]);
            float4 r1 = make_float4(c[4].y + bias[4], c[5].y + bias[5],
                                    c[6].y + bias[6], c[7].y + bias[7]);
            *(float4*)(dstbase + (size_t)(gn0 + 1) * 32 + nc)     = r0;
            *(float4*)(dstbase + (size_t)(gn0 + 1) * 32 + nc + 4) = r1;
        }
    }
}

// ---------------- vectorized aggregation -------------------------------------
template <bool ADD_S_RELU>
__global__ void agg_k(const float* __restrict__ G,
                      const float* __restrict__ S,
                      float* __restrict__ Out) {
    int node = (blockIdx.x * blockDim.x + threadIdx.x) >> 5;
    int lane = threadIdx.x & 31;
    if (node >= NN) return;
    int s = lane >> 3, p = lane & 7;

    const float4* G4 = (const float4*)G;
    int beg = g_rowptr[node], end = g_rowptr[node + 1];

    float4 accA = make_float4(0.f, 0.f, 0.f, 0.f);
    float4 accB = make_float4(0.f, 0.f, 0.f, 0.f);

    for (int base = beg; base < end; base += 32) {
        int cnt = end - base;
        if (cnt > 32) cnt = 32;
        int idx = 0;
        if (lane < cnt) idx = g_csrc[base + lane];
#pragma unroll 4
        for (int j = 0; j < cnt; j += 8) {
            int e0 = __shfl_sync(0xffffffffu, idx, j + s);
            int e1 = __shfl_sync(0xffffffffu, idx, j + 4 + s);
            if (j + s < cnt) {
                float4 v = G4[e0 * 8 + p];
                accA.x += v.x; accA.y += v.y; accA.z += v.z; accA.w += v.w;
            }
            if (j + 4 + s < cnt) {
                float4 v = G4[e1 * 8 + p];
                accB.x += v.x; accB.y += v.y; accB.z += v.z; accB.w += v.w;
            }
        }
    }

    float4 v = make_float4(accA.x + accB.x, accA.y + accB.y,
                           accA.z + accB.z, accA.w + accB.w);
    v.x += __shfl_xor_sync(0xffffffffu, v.x, 8);
    v.y += __shfl_xor_sync(0xffffffffu, v.y, 8);
    v.z += __shfl_xor_sync(0xffffffffu, v.z, 8);
    v.w += __shfl_xor_sync(0xffffffffu, v.w, 8);
    v.x += __shfl_xor_sync(0xffffffffu, v.x, 16);
    v.y += __shfl_xor_sync(0xffffffffu, v.y, 16);
    v.z += __shfl_xor_sync(0xffffffffu, v.z, 16);
    v.w += __shfl_xor_sync(0xffffffffu, v.w, 16);

    if (s == 0) {
        if (ADD_S_RELU) {
            float4 sv = ((const float4*)S)[node * 8 + p];
            v.x = fmaxf(v.x + sv.x, 0.f);
            v.y = fmaxf(v.y + sv.y, 0.f);
            v.z = fmaxf(v.z + sv.z, 0.f);
            v.w = fmaxf(v.w + sv.w, 0.f);
        }
        ((float4*)Out)[node * 8 + p] = v;
    }
}

// ---------------- fused layer GEMM (layers 1,2): out = relu(A@Wn + X@Ws + bn)
// [A|X] @ vstack(Wn,Ws), K=64 chunked as {A, X}. 128 nodes x 32 cols per
// 128-thread block; thread = 8 nodes (4 pairs) x 4 cols via FFMA2.
__global__ void __launch_bounds__(128) fgemm_k(const float* __restrict__ A,
                       const float* __restrict__ X,
                       const float* __restrict__ Wn,
                       const float* __restrict__ Ws,
                       const float* __restrict__ bn,
                       float* __restrict__ Out) {
    __shared__ __align__(16) float xs[32][132];
    __shared__ __align__(16) ull   ws2[64][32];   // [k][col] dup pairs, all K
    __shared__ float bn_s[32];

    int t = threadIdx.x;
    int base = blockIdx.x * 128;
    if (t < 32) bn_s[t] = bn[t];

#pragma unroll
    for (int i = t; i < 2048; i += 128) {
        int k = i >> 5, n = i & 31;
        float w = (k < 32) ? Wn[k * 32 + n] : Ws[(k - 32) * 32 + n];
        ws2[k][n] = dup2(w);
    }

    int tm = t & 15, tn = t >> 4;
    int m0 = tm * 8, n0 = tn * 4;

    ull acc[4][4];
#pragma unroll
    for (int p = 0; p < 4; p++)
#pragma unroll
        for (int j = 0; j < 4; j++) acc[p][j] = 0ull;

    const float4* A4 = (const float4*)A;
    const float4* X4 = (const float4*)X;

#pragma unroll
    for (int c = 0; c < 2; c++) {
        __syncthreads();
#pragma unroll
        for (int e = t; e < 1024; e += 128) {
            int node = e >> 3, g = e & 7;
            int gn = base + node;
            float4 v = make_float4(0.f, 0.f, 0.f, 0.f);
            if (gn < NN) v = (c == 0) ? A4[gn * 8 + g] : X4[gn * 8 + g];
            xs[g * 4 + 0][node] = v.x;
            xs[g * 4 + 1][node] = v.y;
            xs[g * 4 + 2][node] = v.z;
            xs[g * 4 + 3][node] = v.w;
        }
        __syncthreads();
#pragma unroll
        for (int k = 0; k < 32; k++) {
            ulonglong2 a01 = *(const ulonglong2*)&xs[k][m0];
            ulonglong2 a23 = *(const ulonglong2*)&xs[k][m0 + 4];
            ull av[4] = {a01.x, a01.y, a23.x, a23.y};
            const ulonglong2* wr = (const ulonglong2*)&ws2[c * 32 + k][n0];
            ulonglong2 b01 = wr[0], b23 = wr[1];
            ull bv[4] = {b01.x, b01.y, b23.x, b23.y};
#pragma unroll
            for (int p = 0; p < 4; p++)
#pragma unroll
                for (int j = 0; j < 4; j++)
                    acc[p][j] = ffma2(av[p], bv[j], acc[p][j]);
        }
    }

    float bias[4];
#pragma unroll
    for (int j = 0; j < 4; j++) bias[j] = bn_s[n0 + j];

#pragma unroll
    for (int p = 0; p < 4; p++) {
        int gn0 = base + m0 + 2 * p;
        float2 c0 = unpk(acc[p][0]), c1 = unpk(acc[p][1]);
        float2 c2 = unpk(acc[p][2]), c3 = unpk(acc[p][3]);
        if (gn0 < NN) {
            float4 r = make_float4(fmaxf(c0.x + bias[0], 0.f),
                                   fmaxf(c1.x + bias[1], 0.f),
                                   fmaxf(c2.x + bias[2], 0.f),
                                   fmaxf(c3.x + bias[3], 0.f));
            *(float4*)(Out + (size_t)gn0 * 32 + n0) = r;
        }
        if (gn0 + 1 < NN) {
            float4 r = make_float4(fmaxf(c0.y + bias[0], 0.f),
                                   fmaxf(c1.y + bias[1], 0.f),
                                   fmaxf(c2.y + bias[2], 0.f),
                                   fmaxf(c3.y + bias[3], 0.f));
            *(float4*)(Out + (size_t)(gn0 + 1) * 32 + n0) = r;
        }
    }
}

// ---------------- FC phase 1: partial logits from x (k = 0..127) + bias ------
// thread per node; acc packed over class pairs (5 FFMA2 per k).
__global__ void __launch_bounds__(128) fc1_k(const float* __restrict__ X,
                     const float* __restrict__ fcw,
                     const float* __restrict__ fcb,
                     float* __restrict__ partial) {
    __shared__ __align__(16) float w_s[128 * 12];  // row padded to 12 floats
    __shared__ float b_s[12];
    __shared__ float xt[128][33];

    int t = threadIdx.x;
    for (int i = t; i < 128 * 10; i += 128) {
        int k = i / 10, c = i % 10;
        w_s[k * 12 + c] = fcw[k * 10 + c];
    }
    if (t < 10) b_s[t] = fcb[t];

    int node = blockIdx.x * 128 + t;
    ull acc[5];
#pragma unroll
    for (int c = 0; c < 5; c++) acc[c] = 0ull;

#pragma unroll
    for (int j = 0; j < 4; j++) {
        __syncthreads();
        for (int i = t; i < 128 * 32; i += 128) {
            int nl = i >> 5, k = i & 31;
            int gn = blockIdx.x * 128 + nl;
            xt[nl][k] = (gn < NN) ? X[(size_t)gn * 128 + j * 32 + k] : 0.f;
        }
        __syncthreads();
#pragma unroll
        for (int kk = 0; kk < 32; kk++) {
            ull a = dup2(xt[t][kk]);
            const float* wr = &w_s[(j * 32 + kk) * 12];
            ulonglong2 b01 = *(const ulonglong2*)wr;
            ulonglong2 b23 = *(const ulonglong2*)(wr + 4);
            ull b4 = *(const ull*)(wr + 8);
            acc[0] = ffma2(a, b01.x, acc[0]);
            acc[1] = ffma2(a, b01.y, acc[1]);
            acc[2] = ffma2(a, b23.x, acc[2]);
            acc[3] = ffma2(a, b23.y, acc[3]);
            acc[4] = ffma2(a, b4, acc[4]);
        }
    }
    if (node < NN) {
        float2 c[5];
#pragma unroll
        for (int i = 0; i < 5; i++) c[i] = unpk(acc[i]);
        float* dstp = partial + (size_t)node * 10;
        dstp[0] = c[0].x + b_s[0]; dstp[1] = c[0].y + b_s[1];
        dstp[2] = c[1].x + b_s[2]; dstp[3] = c[1].y + b_s[3];
        dstp[4] = c[2].x + b_s[4]; dstp[5] = c[2].y + b_s[5];
        dstp[6] = c[3].x + b_s[6]; dstp[7] = c[3].y + b_s[7];
        dstp[8] = c[4].x + b_s[8]; dstp[9] = c[4].y + b_s[9];
    }
}

// ---------------- FC phase 2: L parts (k = 128..223) + log_softmax -----------
__global__ void __launch_bounds__(128) fc2_k(const float* __restrict__ L0,
                     const float* __restrict__ L1,
                     const float* __restrict__ L2,
                     const float* __restrict__ fcw,
                     const float* __restrict__ partial,
                     float* __restrict__ out) {
    __shared__ __align__(16) float w_s[96 * 12];
    __shared__ float xt[128][33];

    int t = threadIdx.x;
    for (int i = t; i < 96 * 10; i += 128) {
        int k = i / 10, c = i % 10;
        w_s[k * 12 + c] = fcw[(128 + k) * 10 + c];
    }

    int node = blockIdx.x * 128 + t;
    ull acc[5];
#pragma unroll
    for (int c = 0; c < 5; c++) acc[c] = 0ull;

#pragma unroll
    for (int j = 0; j < 3; j++) {
        __syncthreads();
        const float* srcp = (j == 0) ? L0 : (j == 1) ? L1 : L2;
        for (int i = t; i < 128 * 32; i += 128) {
            int nl = i >> 5, k = i & 31;
            int gn = blockIdx.x * 128 + nl;
            xt[nl][k] = (gn < NN) ? srcp[(size_t)gn * 32 + k] : 0.f;
        }
        __syncthreads();
#pragma unroll
        for (int kk = 0; kk < 32; kk++) {
            ull a = dup2(xt[t][kk]);
            const float* wr = &w_s[(j * 32 + kk) * 12];
            ulonglong2 b01 = *(const ulonglong2*)wr;
            ulonglong2 b23 = *(const ulonglong2*)(wr + 4);
            ull b4 = *(const ull*)(wr + 8);
            acc[0] = ffma2(a, b01.x, acc[0]);
            acc[1] = ffma2(a, b01.y, acc[1]);
            acc[2] = ffma2(a, b23.x, acc[2]);
            acc[3] = ffma2(a, b23.y, acc[3]);
            acc[4] = ffma2(a, b4, acc[4]);
        }
    }

    if (node < NN) {
        float logit[10];
        float2 c[5];
#pragma unroll
        for (int i = 0; i < 5; i++) c[i] = unpk(acc[i]);
        const float* pp = partial + (size_t)node * 10;
        logit[0] = c[0].x + pp[0]; logit[1] = c[0].y + pp[1];
        logit[2] = c[1].x + pp[2]; logit[3] = c[1].y + pp[3];
        logit[4] = c[2].x + pp[4]; logit[5] = c[2].y + pp[5];
        logit[6] = c[3].x + pp[6]; logit[7] = c[3].y + pp[7];
        logit[8] = c[4].x + pp[8]; logit[9] = c[4].y + pp[9];
        float m = logit[0];
#pragma unroll
        for (int cc = 1; cc < 10; cc++) m = fmaxf(m, logit[cc]);
        float ssum = 0.f;
#pragma unroll
        for (int cc = 0; cc < 10; cc++) ssum += expf(logit[cc] - m);
        float l = logf(ssum);
#pragma unroll
        for (int cc = 0; cc < 10; cc++)
            out[(size_t)node * 10 + cc] = logit[cc] - m - l;
    }
}

// ---------------- launch -----------------------------------------------------
extern "C" void kernel_launch(void* const* d_in, const int* in_sizes, int n_in,
                              void* d_out, int out_size) {
    const float* x   = (const float*)d_in[0];
    const int*   src = (const int*)d_in[1];
    const int*   dst = (const int*)d_in[2];
    const float* Wn0 = (const float*)d_in[3];
    const float* bn0 = (const float*)d_in[4];
    const float* Ws0 = (const float*)d_in[5];
    const float* Wn1 = (const float*)d_in[6];
    const float* bn1 = (const float*)d_in[7];
    const float* Ws1 = (const float*)d_in[8];
    const float* Wn2 = (const float*)d_in[9];
    const float* bn2 = (const float*)d_in[10];
    const float* Ws2 = (const float*)d_in[11];
    const float* fcw = (const float*)d_in[12];
    const float* fcb = (const float*)d_in[13];
    float* out = (float*)d_out;

    void *pH, *pA, *pL, *pP, *pDeg;
    cudaGetSymbolAddress(&pH, g_H);
    cudaGetSymbolAddress(&pA, g_A);
    cudaGetSymbolAddress(&pL, g_L);
    cudaGetSymbolAddress(&pP, g_P);
    cudaGetSymbolAddress(&pDeg, g_deg);
    float* H  = (float*)pH;
    float* A  = (float*)pA;
    float* L0 = (float*)pL;
    float* L1 = L0 + (size_t)NN * 32;
    float* L2 = L1 + (size_t)NN * 32;
    float* P  = (float*)pP;

    const int gemmBlocks = (NN + 127) / 128;   // 782
    const int aggBlocks  = (NN + 7) / 8;       // 12500 (warp per node)

    // Fork CSR build onto a side stream, overlapped with gemm0 + fc1.
    cudaStream_t s2;
    cudaStreamCreateWithFlags(&s2, cudaStreamNonBlocking);
    cudaEvent_t evF, evJ;
    cudaEventCreateWithFlags(&evF, cudaEventDisableTiming);
    cudaEventCreateWithFlags(&evJ, cudaEventDisableTiming);

    cudaEventRecord(evF, 0);
    cudaStreamWaitEvent(s2, evF, 0);

    // CSR chain on s2
    cudaMemsetAsync(pDeg, 0, NN * sizeof(int), s2);
    count_k<<<(EE / 4 + 255) / 256, 256, 0, s2>>>(dst);
    scan_k<<<1, 1024, 0, s2>>>();
    fill_k<<<(EE / 4 + 255) / 256, 256, 0, s2>>>(src, dst);
    cudaEventRecord(evJ, s2);

    // main stream: gemm0 (H = x@Wn0, A = x@Ws0+bn0) and FC x-part, overlapped
    gemm0_k<<<gemmBlocks, 128>>>(x, Wn0, Ws0, bn0, H, A);
    fc1_k<<<gemmBlocks, 128>>>(x, fcw, fcb, P);

    cudaStreamWaitEvent(0, evJ, 0);

    // layer 0: L0 = relu(segsum(H[src]) + S)
    agg_k<true><<<aggBlocks, 256>>>(H, A, L0);

    // layer 1: A = segsum(L0[src]);  L1 = relu(A@Wn1 + L0@Ws1 + bn1)
    agg_k<false><<<aggBlocks, 256>>>(L0, nullptr, A);
    fgemm_k<<<gemmBlocks, 128>>>(A, L0, Wn1, Ws1, bn1, L1);

    // layer 2
    agg_k<false><<<aggBlocks, 256>>>(L1, nullptr, A);
    fgemm_k<<<gemmBlocks, 128>>>(A, L1, Wn2, Ws2, bn2, L2);

    // FC phase 2 + log_softmax
    fc2_k<<<gemmBlocks, 128>>>(L0, L1, L2, fcw, P, out);
}